// round 16
// baseline (speedup 1.0000x reference)
#include <cuda_runtime.h>
#include <math.h>

#define SOSID 2
#define EPSF  1e-6f

typedef unsigned long long u64;

// ---------------- persistent device state ----------------
__device__ float g_phi_hs[3200*512];
__device__ float g_phi_fds[3200*512];
__device__ float g_zx[2080*2048];
__device__ float g_encT[32*512*104];
__device__ float g_hbuf[2][32*512];
__device__ float g_cbuf[2][32*512];
__device__ float g_ot[32*512];
__device__ float g_gamma[32*512];
__device__ float g_alpha[32*512];
__device__ float g_ctx[32*512];
__device__ float g_att_all[2080*512];  // att for ALL steps
__device__ float g_zp[8*4*16384];      // LSTM partials: [ks][gate][b*512+h]
__device__ int          g_cnt;
__device__ volatile int g_gen;

// ---------------- helpers ----------------
__device__ __forceinline__ u64 pk2(float lo, float hi){
    u64 r; asm("mov.b64 %0, {%1,%2};" : "=l"(r) : "f"(lo), "f"(hi)); return r;
}
__device__ __forceinline__ void upk2(u64 v, float& lo, float& hi){
    asm("mov.b64 {%0,%1}, %2;" : "=f"(lo), "=f"(hi) : "l"(v));
}
__device__ __forceinline__ u64 ffma2(u64 a, u64 b, u64 c){
    u64 r; asm("fma.rn.f32x2 %0, %1, %2, %3;" : "=l"(r) : "l"(a), "l"(b), "l"(c)); return r;
}
__device__ __forceinline__ u64 fadd2(u64 a, u64 b){
    u64 r; asm("add.rn.f32x2 %0, %1, %2;" : "=l"(r) : "l"(a), "l"(b)); return r;
}
__device__ __forceinline__ float sigf(float x){ return 1.f/(1.f+expf(-x)); }
__device__ __forceinline__ void pref(const void* p){
    asm volatile("prefetch.global.L2 [%0];" :: "l"(p));
}

// global barrier (gridDim.x co-resident blocks)
__device__ __forceinline__ void gsync(){
    __threadfence();
    __syncthreads();
    if (threadIdx.x == 0){
        int g = g_gen;
        if (atomicAdd(&g_cnt, 1) == (int)gridDim.x - 1){
            g_cnt = 0;
            __threadfence();
            g_gen = g + 1;
        } else {
            while (g_gen == g) { __nanosleep(20); }
        }
    }
    __syncthreads();
}

// ---------------- inner-loop building blocks ----------------
__device__ __forceinline__ void load4v(float4 (&w)[4], const float*& wp, int ldw){
    #pragma unroll
    for (int i=0;i<4;i++){ w[i] = *(const float4*)wp; wp += ldw; }
}
__device__ __forceinline__ void comp4v(u64 (&acc)[8][4], const float*& ap, const float4 (&w)[4]){
    #pragma unroll
    for (int i=0;i<4;i++){
        u64 b0=pk2(w[i].x,w[i].x), b1=pk2(w[i].y,w[i].y),
            b2=pk2(w[i].z,w[i].z), b3=pk2(w[i].w,w[i].w);
        u64 aa[8];
        #pragma unroll
        for (int m=0;m<8;m++) aa[m]=((const u64*)ap)[m];
        ap += 36;
        #pragma unroll
        for (int m=0;m<8;m++){
            acc[m][0]=ffma2(aa[m],b0,acc[m][0]);
            acc[m][1]=ffma2(aa[m],b1,acc[m][1]);
            acc[m][2]=ffma2(aa[m],b2,acc[m][2]);
            acc[m][3]=ffma2(aa[m],b3,acc[m][3]);
        }
    }
}
__device__ __forceinline__ void comp4v4(u64 (&acc)[4][4], const float*& ap, const float4 (&w)[4]){
    #pragma unroll
    for (int i=0;i<4;i++){
        u64 b0=pk2(w[i].x,w[i].x), b1=pk2(w[i].y,w[i].y),
            b2=pk2(w[i].z,w[i].z), b3=pk2(w[i].w,w[i].w);
        u64 aa[4];
        #pragma unroll
        for (int m=0;m<4;m++) aa[m]=((const u64*)ap)[m];
        ap += 36;
        #pragma unroll
        for (int m=0;m<4;m++){
            acc[m][0]=ffma2(aa[m],b0,acc[m][0]);
            acc[m][1]=ffma2(aa[m],b1,acc[m][1]);
            acc[m][2]=ffma2(aa[m],b2,acc[m][2]);
            acc[m][3]=ffma2(aa[m],b3,acc[m][3]);
        }
    }
}
__device__ __forceinline__ void load4g(float (&w)[16], const float*& wp){
    #pragma unroll
    for (int i=0;i<4;i++){
        w[i*4+0]=wp[0]; w[i*4+1]=wp[512]; w[i*4+2]=wp[1024]; w[i*4+3]=wp[1536];
        wp += 2048;
    }
}
__device__ __forceinline__ void comp4g2(u64 (&acc)[2][4], const float*& ap, const float (&w)[16]){
    #pragma unroll
    for (int i=0;i<4;i++){
        u64 b0=pk2(w[i*4+0],w[i*4+0]), b1=pk2(w[i*4+1],w[i*4+1]),
            b2=pk2(w[i*4+2],w[i*4+2]), b3=pk2(w[i*4+3],w[i*4+3]);
        u64 a0=((const u64*)ap)[0], a1=((const u64*)ap)[1];
        ap += 36;
        acc[0][0]=ffma2(a0,b0,acc[0][0]); acc[1][0]=ffma2(a1,b0,acc[1][0]);
        acc[0][1]=ffma2(a0,b1,acc[0][1]); acc[1][1]=ffma2(a1,b1,acc[1][1]);
        acc[0][2]=ffma2(a0,b2,acc[0][2]); acc[1][2]=ffma2(a1,b2,acc[1][2]);
        acc[0][3]=ffma2(a0,b3,acc[0][3]); acc[1][3]=ffma2(a1,b3,acc[1][3]);
    }
}

// ================= precompute GEMM (device fn, proven) ====
template<int K, int AMODE, int EPI>
__device__ void dev_g32(float* sm,
    const float* __restrict__ W, const float* __restrict__ Bv,
    const float* __restrict__ A, int lda, int ldw,
    const float* __restrict__ p1, int rowBase, int tt, int colblk)
{
    const int tid = threadIdx.x;
    const int cg  = tid & 63;
    const int rh  = (tid >> 6) & 1;
    const int ks  = tid >> 7;

    for (int idx = tid; idx < 32*K; idx += 256){
        int m = idx / K, k = idx - m*K;
        float v;
        if (AMODE==0) v = A[(size_t)(rowBase+m)*lda + k];
        else          v = (tt==0) ? A[SOSID*512 + k]
                                  : p1[((size_t)m*64 + (tt-1))*512 + k];
        sm[k*36 + m] = v;
    }
    __syncthreads();

    u64 acc[8][4];
    #pragma unroll
    for (int i=0;i<8;i++){ acc[i][0]=0; acc[i][1]=0; acc[i][2]=0; acc[i][3]=0; }

    const float* wp = W + (size_t)(ks*(K/2))*ldw + colblk*256 + cg*4;
    const float* ap = sm + (ks*(K/2))*36 + rh*16;
    const int NT2 = ((K/2)/4)/2;

    float4 wa[4], wb[4];
    load4v(wa, wp, ldw);
    #pragma unroll 1
    for (int j=0;j<NT2-1;j++){
        load4v(wb, wp, ldw);
        comp4v(acc, ap, wa);
        load4v(wa, wp, ldw);
        comp4v(acc, ap, wb);
    }
    load4v(wb, wp, ldw);
    comp4v(acc, ap, wa);
    comp4v(acc, ap, wb);

    __syncthreads();
    u64* red = (u64*)sm;
    u64* mr  = red + (size_t)tid*33;
    #pragma unroll
    for (int m2=0;m2<8;m2++){
        mr[4*m2+0]=acc[m2][0]; mr[4*m2+1]=acc[m2][1];
        mr[4*m2+2]=acc[m2][2]; mr[4*m2+3]=acc[m2][3];
    }
    __syncthreads();
    if (ks == 0){
        const u64* pr = red + (size_t)(tid + 128)*33;
        #pragma unroll
        for (int m2=0;m2<8;m2++){
            acc[m2][0]=fadd2(acc[m2][0],pr[4*m2+0]);
            acc[m2][1]=fadd2(acc[m2][1],pr[4*m2+1]);
            acc[m2][2]=fadd2(acc[m2][2],pr[4*m2+2]);
            acc[m2][3]=fadd2(acc[m2][3],pr[4*m2+3]);
        }
        int c0 = colblk*256 + cg*4;
        #pragma unroll
        for (int m2=0;m2<8;m2++){
            float v0[4], v1[4];
            upk2(acc[m2][0],v0[0],v1[0]); upk2(acc[m2][1],v0[1],v1[1]);
            upk2(acc[m2][2],v0[2],v1[2]); upk2(acc[m2][3],v0[3],v1[3]);
            #pragma unroll
            for (int r=0;r<2;r++){
                int row = rowBase + rh*16 + 2*m2 + r;
                const float* vv = r ? v1 : v0;
                #pragma unroll
                for (int j=0;j<4;j++){
                    int c = c0 + j;
                    float x = vv[j] + Bv[c];
                    if (EPI==0)      g_phi_hs [(size_t)row*512 +c] = tanhf(x);
                    else if (EPI==1) g_phi_fds[(size_t)row*512 +c] = tanhf(x);
                    else             g_zx     [(size_t)row*2048+c] = x;
                }
            }
        }
    }
    __syncthreads();
}

__global__ void __launch_bounds__(256)
pre_all(const float* __restrict__ h0,  const float* __restrict__ c0,
        const float* __restrict__ enc, const float* __restrict__ fld,
        const float* __restrict__ emb, const float* __restrict__ inp,
        const float* __restrict__ lW,  const float* __restrict__ lb,
        const float* __restrict__ Wh,  const float* __restrict__ bh,
        const float* __restrict__ Wf,  const float* __restrict__ bf)
{
    extern __shared__ float sm[];
    const int task = blockIdx.x;
    const int tid  = threadIdx.x;

    if (task < 200){
        dev_g32<512,0,0>(sm, Wh, bh, enc, 512, 512, nullptr, (task>>1)*32, 0, task&1);
    } else if (task < 400){
        int x = task - 200;
        dev_g32<64,0,1>(sm, Wf, bf, fld, 64, 512, nullptr, (x>>1)*32, 0, x&1);
    } else if (task < 920){
        int x = task - 400;
        dev_g32<512,1,2>(sm, lW, lb, emb, 512, 2048, inp, (x>>3)*32, x>>3, x&7);
    } else {
        const int gt = (task-920)*256 + tid, gs = 80*256;
        for (int i=gt; i<16384; i+=gs){ g_hbuf[0][i]=h0[i]; g_cbuf[0][i]=c0[i]; }
        for (int i=gt; i<32*512*104; i+=gs){
            int l=i%104; int hh=(i/104)&511; int b=i/(104*512);
            g_encT[i] = (l<100) ? enc[((size_t)b*100+l)*512+hh] : 0.f;
        }
    }
}

// ================= fused chain kernel: 4 phases, 4 grid barriers ========
__global__ void __launch_bounds__(256, 1)
chain_k(const float* __restrict__ lWh,
        const float* __restrict__ Ws, const float* __restrict__ bs,
        const float* __restrict__ Wr, const float* __restrict__ br,
        const float* __restrict__ Wo, const float* __restrict__ bo,
        const int* __restrict__ lens, int t)
{
    extern __shared__ float sm[];
    const int blk = blockIdx.x;
    const int tid = threadIdx.x;
    const int warp = tid >> 5, lane = tid & 31;
    const int pb = t & 1, cb = pb ^ 1;

    // ---------- L2 prefetch for the merged attention phase ----------
    {
        const int b = blk >> 2, hq = blk & 3;
        const char* p1 = (const char*)(g_phi_hs  + (size_t)b*100*512);
        const char* p2 = (const char*)(g_phi_fds + (size_t)b*100*512);
        for (int off = tid*128; off < 100*512*4; off += 256*128){
            pref(p1 + off);
            pref(p2 + off);
        }
        const char* pe = (const char*)(g_encT + ((size_t)b*512 + hq*128)*104);
        for (int off = tid*128; off < 128*104*4; off += 256*128)
            pref(pe + off);
    }

    // ---------- P0a: LSTM partials. 128 blocks = 16 h-groups x 8 K-splits ------
    {
        const int hbase = (blk >> 3) * 32;
        const int kq    = blk & 7;
        const int k0    = kq * 64;

        for (int idx = tid; idx < 32*64; idx += 256){
            int m = idx >> 6, k = idx & 63;
            sm[k*36 + m] = g_hbuf[pb][m*512 + k0 + k];
        }
        __syncthreads();

        const int hc = tid & 31;
        const int rg = tid >> 5;

        u64 acc[2][4];
        #pragma unroll
        for (int i=0;i<2;i++){ acc[i][0]=0; acc[i][1]=0; acc[i][2]=0; acc[i][3]=0; }

        const float* wp = lWh + (size_t)k0*2048 + hbase + hc;
        const float* ap = sm + rg*4;

        float wa[16], wb[16];
        load4g(wa, wp);
        #pragma unroll 1
        for (int j=0;j<7;j++){
            load4g(wb, wp);
            comp4g2(acc, ap, wa);
            load4g(wa, wp);
            comp4g2(acc, ap, wb);
        }
        load4g(wb, wp);
        comp4g2(acc, ap, wa);
        comp4g2(acc, ap, wb);

        const int h = hbase + hc;
        #pragma unroll
        for (int p=0;p<2;p++){
            float lo[4], hi[4];
            #pragma unroll
            for (int g=0;g<4;g++) upk2(acc[p][g], lo[g], hi[g]);
            #pragma unroll
            for (int r=0;r<2;r++){
                int b = rg*4 + p*2 + r;
                const float* v = r ? hi : lo;
                #pragma unroll
                for (int g=0;g<4;g++)
                    g_zp[(size_t)(kq*4+g)*16384 + b*512 + h] = v[g];
            }
        }
    }
    gsync();

    // ---------- P0b: gate math + state update ----------------
    if (tid < 128){
        int e = blk*128 + tid;
        int b = e >> 9, h = e & 511;
        float vi=0.f, vj=0.f, vf=0.f, vo=0.f;
        #pragma unroll
        for (int ks2=0; ks2<8; ks2++){
            vi += g_zp[(size_t)(ks2*4+0)*16384 + e];
            vj += g_zp[(size_t)(ks2*4+1)*16384 + e];
            vf += g_zp[(size_t)(ks2*4+2)*16384 + e];
            vo += g_zp[(size_t)(ks2*4+3)*16384 + e];
        }
        const float* zxp = g_zx + ((size_t)(t*32+b))*2048 + h;
        vi += zxp[0]; vj += zxp[512]; vf += zxp[1024]; vo += zxp[1536];
        float cp = g_cbuf[pb][e];
        float hp = g_hbuf[pb][e];
        float cn = sigf(vf+1.f)*cp + sigf(vi)*tanhf(vj);
        float hn = sigf(vo)*tanhf(cn);
        bool fin = (t>0) && (t-1 >= lens[b]);
        g_ot[e]       = fin ? 0.f : hn;
        g_hbuf[cb][e] = fin ? hp  : hn;
        g_cbuf[cb][e] = fin ? cp  : cn;
    }
    gsync();

    // ---------- P1: gamma/alpha. 128 blocks x 8 cols, 32-way K split -----------
    {
        for (int idx = tid; idx < 32*512; idx += 256){
            int m = idx >> 9, k = idx & 511;
            sm[k*36 + m] = g_ot[m*512 + k];
        }
        __syncthreads();

        const int dir = blk >> 6;
        const int colbase = (blk & 63) * 8;
        const float* W  = dir ? Wr : Ws;
        const float* Bv = dir ? br : bs;
        float* dst = dir ? g_alpha : g_gamma;

        const int cq = tid & 1;
        const int rq = (tid >> 1) & 3;
        const int ks = tid >> 3;

        u64 acc[4][4];
        #pragma unroll
        for (int i=0;i<4;i++){ acc[i][0]=0; acc[i][1]=0; acc[i][2]=0; acc[i][3]=0; }

        const float* wp = W + (size_t)(ks*16)*512 + colbase + cq*4;
        const float* ap = sm + (ks*16)*36 + rq*8;

        float4 wa[4], wb[4];
        load4v(wa, wp, 512);
        load4v(wb, wp, 512);
        comp4v4(acc, ap, wa);
        load4v(wa, wp, 512);
        comp4v4(acc, ap, wb);
        load4v(wb, wp, 512);
        comp4v4(acc, ap, wa);
        comp4v4(acc, ap, wb);

        __syncthreads();
        u64* red = (u64*)sm;
        u64* mr  = red + (size_t)tid*17;
        #pragma unroll
        for (int m2=0;m2<4;m2++){
            mr[4*m2+0]=acc[m2][0]; mr[4*m2+1]=acc[m2][1];
            mr[4*m2+2]=acc[m2][2]; mr[4*m2+3]=acc[m2][3];
        }
        __syncthreads();
        for (int s=16; s>=1; s>>=1){
            if (ks < s){
                const u64* pr = red + (size_t)(tid + s*8)*17;
                #pragma unroll
                for (int m2=0;m2<4;m2++){
                    acc[m2][0]=fadd2(acc[m2][0],pr[4*m2+0]);
                    acc[m2][1]=fadd2(acc[m2][1],pr[4*m2+1]);
                    acc[m2][2]=fadd2(acc[m2][2],pr[4*m2+2]);
                    acc[m2][3]=fadd2(acc[m2][3],pr[4*m2+3]);
                }
                if (s>1){
                    #pragma unroll
                    for (int m2=0;m2<4;m2++){
                        mr[4*m2+0]=acc[m2][0]; mr[4*m2+1]=acc[m2][1];
                        mr[4*m2+2]=acc[m2][2]; mr[4*m2+3]=acc[m2][3];
                    }
                }
            }
            __syncthreads();
        }
        if (ks == 0){
            const int c0 = colbase + cq*4;
            #pragma unroll
            for (int m2=0;m2<4;m2++){
                float v0[4], v1[4];
                upk2(acc[m2][0],v0[0],v1[0]); upk2(acc[m2][1],v0[1],v1[1]);
                upk2(acc[m2][2],v0[2],v1[2]); upk2(acc[m2][3],v0[3],v1[3]);
                #pragma unroll
                for (int r=0;r<2;r++){
                    int row = rq*8 + 2*m2 + r;
                    const float* vv = r ? v1 : v0;
                    #pragma unroll
                    for (int j=0;j<4;j++){
                        int c = c0 + j;
                        dst[row*512 + c] = tanhf(vv[j] + Bv[c]);
                    }
                }
            }
        }
    }
    gsync();

    // ---------- P23: scores (all 100, redundant x4) + softmax + ctx quarter ----
    {
        __shared__ float4 sg4[128], sa4[128];
        __shared__ float sh2[100], sf2[100], sw2[104], aux2[3];
        const int b  = blk >> 2;
        const int hq = blk & 3;
        if (tid < 128){
            sg4[tid] = ((const float4*)(g_gamma + b*512))[tid];
            sa4[tid] = ((const float4*)(g_alpha + b*512))[tid];
        }
        __syncthreads();
        for (int l = warp; l < 100; l += 8){
            const float4* ph = (const float4*)(g_phi_hs  + ((size_t)b*100 + l)*512);
            const float4* pf = (const float4*)(g_phi_fds + ((size_t)b*100 + l)*512);
            float s1=0.f, s2=0.f;
            #pragma unroll
            for (int i=0;i<4;i++){
                float4 a = ph[lane + 32*i];
                float4 g = sg4[lane + 32*i];
                s1 += a.x*g.x + a.y*g.y + a.z*g.z + a.w*g.w;
                float4 c = pf[lane + 32*i];
                float4 d = sa4[lane + 32*i];
                s2 += c.x*d.x + c.y*d.y + c.z*d.z + c.w*d.w;
            }
            #pragma unroll
            for (int o=16;o;o>>=1){ s1 += __shfl_xor_sync(~0u,s1,o); s2 += __shfl_xor_sync(~0u,s2,o); }
            if (lane==0){ sh2[l]=s1; sf2[l]=s2; }
        }
        __syncthreads();

        if (warp < 2){
            float* s = warp ? sf2 : sh2;
            float mx = -1e30f;
            for (int l=lane;l<100;l+=32) mx = fmaxf(mx, s[l]);
            #pragma unroll
            for (int o=16;o;o>>=1) mx = fmaxf(mx, __shfl_xor_sync(~0u,mx,o));
            float sum = 0.f;
            for (int l=lane;l<100;l+=32){ float e = expf(s[l]-mx); s[l]=e; sum+=e; }
            #pragma unroll
            for (int o=16;o;o>>=1) sum += __shfl_xor_sync(~0u,sum,o);
            if (lane==0) aux2[warp] = EPSF + sum;
        }
        __syncthreads();
        if (warp == 0){
            float d1 = aux2[0], d2 = aux2[1];
            float wsum = 0.f;
            for (int l=lane;l<100;l+=32){ float w = (sh2[l]/d1)*(sf2[l]/d2); sw2[l]=w; wsum += w; }
            #pragma unroll
            for (int o=16;o;o>>=1) wsum += __shfl_xor_sync(~0u,wsum,o);
            if (lane==0) aux2[2] = EPSF + wsum;
        }
        __syncthreads();
        if (warp == 0){
            float d = aux2[2];
            for (int l=lane;l<100;l+=32) sw2[l] = sw2[l]/d;
            if (lane < 4) sw2[100+lane] = 0.f;
        }
        __syncthreads();
        if (tid < 128){
            int h = hq*128 + tid;
            const float4* e = (const float4*)(g_encT + ((size_t)b*512 + h)*104);
            float c2 = 0.f;
            #pragma unroll
            for (int l4=0; l4<26; l4++){
                float4 ev = e[l4];
                int l = l4*4;
                c2 += sw2[l+0]*ev.x + sw2[l+1]*ev.y + sw2[l+2]*ev.z + sw2[l+3]*ev.w;
            }
            g_ctx[b*512+h] = c2;
        }
        __syncthreads();
    }
    gsync();

    // ---------- P4: att(t). 128 blocks x 4 cols, K=1024, 64-way K split --------
    {
        for (int idx = tid; idx < 32*1024; idx += 256){
            int m = idx >> 10, k = idx & 1023;
            float v = (k < 512) ? g_ctx[m*512+k] : g_ot[m*512+k-512];
            sm[k*36 + m] = v;
        }
        __syncthreads();

        const int colbase = blk * 4;
        const int rq = tid & 3;
        const int ks = tid >> 2;

        u64 acc[4][4];
        #pragma unroll
        for (int i=0;i<4;i++){ acc[i][0]=0; acc[i][1]=0; acc[i][2]=0; acc[i][3]=0; }

        const float* wp = Wo + (size_t)(ks*16)*512 + colbase;
        const float* ap = sm + (ks*16)*36 + rq*8;

        float4 wa[4], wb[4];
        load4v(wa, wp, 512);
        load4v(wb, wp, 512);
        comp4v4(acc, ap, wa);
        load4v(wa, wp, 512);
        comp4v4(acc, ap, wb);
        load4v(wb, wp, 512);
        comp4v4(acc, ap, wa);
        comp4v4(acc, ap, wb);

        __syncthreads();
        u64* red = (u64*)sm;
        u64* mr  = red + (size_t)tid*17;
        #pragma unroll
        for (int m2=0;m2<4;m2++){
            mr[4*m2+0]=acc[m2][0]; mr[4*m2+1]=acc[m2][1];
            mr[4*m2+2]=acc[m2][2]; mr[4*m2+3]=acc[m2][3];
        }
        __syncthreads();
        for (int s=32; s>=1; s>>=1){
            if (ks < s){
                const u64* pr = red + (size_t)(tid + s*4)*17;
                #pragma unroll
                for (int m2=0;m2<4;m2++){
                    acc[m2][0]=fadd2(acc[m2][0],pr[4*m2+0]);
                    acc[m2][1]=fadd2(acc[m2][1],pr[4*m2+1]);
                    acc[m2][2]=fadd2(acc[m2][2],pr[4*m2+2]);
                    acc[m2][3]=fadd2(acc[m2][3],pr[4*m2+3]);
                }
                if (s>1){
                    #pragma unroll
                    for (int m2=0;m2<4;m2++){
                        mr[4*m2+0]=acc[m2][0]; mr[4*m2+1]=acc[m2][1];
                        mr[4*m2+2]=acc[m2][2]; mr[4*m2+3]=acc[m2][3];
                    }
                }
            }
            __syncthreads();
        }
        if (ks == 0){
            float* dst = g_att_all + (size_t)t*16384;
            #pragma unroll
            for (int m2=0;m2<4;m2++){
                float v0[4], v1[4];
                upk2(acc[m2][0],v0[0],v1[0]); upk2(acc[m2][1],v0[1],v1[1]);
                upk2(acc[m2][2],v0[2],v1[2]); upk2(acc[m2][3],v0[3],v1[3]);
                #pragma unroll
                for (int r=0;r<2;r++){
                    int row = rq*8 + 2*m2 + r;
                    bool fin = (t>0) && (t-1 >= lens[row]);
                    const float* vv = r ? v1 : v0;
                    #pragma unroll
                    for (int j=0;j<4;j++){
                        int c = colbase + j;
                        float v = tanhf(vv[j] + bo[c]);
                        dst[row*512 + c] = fin ? 0.f : v;
                    }
                }
            }
        }
    }
}

// ---- logits chunk: grid 250 x 256; 128 cols/block for nt steps ----
__global__ void __launch_bounds__(256)
logits_chunk(const float* __restrict__ oW, const float* __restrict__ ob,
             const int* __restrict__ lens, float* __restrict__ out, int t0, int nt)
{
    extern __shared__ float sm[];
    const int tid = threadIdx.x, blk = blockIdx.x;
    const int cg = tid & 31;
    const int rh = (tid >> 5) & 1;
    const int ks = tid >> 6;

    for (int tt = t0; tt < t0 + nt; tt++){
        const float* attb = g_att_all + (size_t)tt*16384;
        __syncthreads();
        for (int idx = tid; idx < 32*512; idx += 256){
            int m = idx >> 9, k = idx & 511;
            sm[k*36 + m] = attb[m*512 + k];
        }
        __syncthreads();

        u64 acc[8][4];
        #pragma unroll
        for (int i=0;i<8;i++){ acc[i][0]=0; acc[i][1]=0; acc[i][2]=0; acc[i][3]=0; }

        const float* wp = oW + (size_t)(ks*128)*32000 + blk*128 + cg*4;
        const float* ap = sm + (ks*128)*36 + rh*16;

        float4 wa[4], wb[4];
        load4v(wa, wp, 32000);
        #pragma unroll 1
        for (int j=0;j<15;j++){
            load4v(wb, wp, 32000);
            comp4v(acc, ap, wa);
            load4v(wa, wp, 32000);
            comp4v(acc, ap, wb);
        }
        load4v(wb, wp, 32000);
        comp4v(acc, ap, wa);
        comp4v(acc, ap, wb);

        __syncthreads();
        u64* red = (u64*)sm;
        u64* mr  = red + (size_t)tid*33;
        #pragma unroll
        for (int m2=0;m2<8;m2++){
            mr[4*m2+0]=acc[m2][0]; mr[4*m2+1]=acc[m2][1];
            mr[4*m2+2]=acc[m2][2]; mr[4*m2+3]=acc[m2][3];
        }
        __syncthreads();
        for (int s=2; s>=1; s>>=1){
            if (ks < s){
                const u64* pr = red + (size_t)(tid + s*64)*33;
                #pragma unroll
                for (int m2=0;m2<8;m2++){
                    acc[m2][0]=fadd2(acc[m2][0],pr[4*m2+0]);
                    acc[m2][1]=fadd2(acc[m2][1],pr[4*m2+1]);
                    acc[m2][2]=fadd2(acc[m2][2],pr[4*m2+2]);
                    acc[m2][3]=fadd2(acc[m2][3],pr[4*m2+3]);
                }
                if (s>1){
                    #pragma unroll
                    for (int m2=0;m2<8;m2++){
                        mr[4*m2+0]=acc[m2][0]; mr[4*m2+1]=acc[m2][1];
                        mr[4*m2+2]=acc[m2][2]; mr[4*m2+3]=acc[m2][3];
                    }
                }
            }
            __syncthreads();
        }
        if (ks == 0){
            const int c0 = blk*128 + cg*4;
            #pragma unroll
            for (int m2=0;m2<8;m2++){
                float v0[4], v1[4];
                upk2(acc[m2][0],v0[0],v1[0]); upk2(acc[m2][1],v0[1],v1[1]);
                upk2(acc[m2][2],v0[2],v1[2]); upk2(acc[m2][3],v0[3],v1[3]);
                #pragma unroll
                for (int r=0;r<2;r++){
                    int row = rh*16 + 2*m2 + r;
                    bool fin = (tt>0) && (tt-1 >= lens[row]);
                    const float* vv = r ? v1 : v0;
                    float* op = out + (size_t)row*2080000 + (size_t)tt*32000 + c0;
                    #pragma unroll
                    for (int j=0;j<4;j++)
                        op[j] = fin ? 0.f : (vv[j] + ob[c0+j]);
                }
            }
        }
    }
}

// ---- final h/c ----
__global__ void fin_k(float* __restrict__ out)
{
    int i = blockIdx.x*256 + threadIdx.x;
    if (i < 16384){
        out[66560000 + i]         = g_hbuf[1][i];
        out[66560000 + 16384 + i] = g_cbuf[1][i];
    }
}

// ---------------- host ----------------
extern "C" void kernel_launch(void* const* d_in, const int* in_sizes, int n_in,
                              void* d_out, int out_size)
{
    const float* h0   = (const float*)d_in[0];
    const float* c0   = (const float*)d_in[1];
    const float* inp  = (const float*)d_in[2];
    const float* enc  = (const float*)d_in[3];
    const float* fld  = (const float*)d_in[4];
    const float* emb  = (const float*)d_in[5];
    const float* lW   = (const float*)d_in[6];
    const float* lb   = (const float*)d_in[7];
    const float* Wh   = (const float*)d_in[8];
    const float* bh   = (const float*)d_in[9];
    const float* Ws   = (const float*)d_in[10];
    const float* bs   = (const float*)d_in[11];
    const float* Wr   = (const float*)d_in[12];
    const float* br   = (const float*)d_in[13];
    const float* Wf   = (const float*)d_in[14];
    const float* bf   = (const float*)d_in[15];
    const float* Wo   = (const float*)d_in[16];
    const float* bo   = (const float*)d_in[17];
    const float* oW   = (const float*)d_in[18];
    const float* ob   = (const float*)d_in[19];
    const int*   lens = (const int*)  d_in[20];
    float* out = (float*)d_out;

    const int SM_PRE   = 512*36*4;      // 73728
    const int SM_CHAIN = 1024*36*4;     // 147456
    const int SM_LOG   = 512*36*4;      // 73728

    cudaFuncSetAttribute((const void*)pre_all,      cudaFuncAttributeMaxDynamicSharedMemorySize, SM_PRE);
    cudaFuncSetAttribute((const void*)chain_k,      cudaFuncAttributeMaxDynamicSharedMemorySize, SM_CHAIN);
    cudaFuncSetAttribute((const void*)logits_chunk, cudaFuncAttributeMaxDynamicSharedMemorySize, SM_LOG);

    cudaStream_t s2;
    cudaStreamCreateWithFlags(&s2, cudaStreamNonBlocking);
    cudaEvent_t eC[6], eJ;
    for (int i=0;i<6;i++) cudaEventCreateWithFlags(&eC[i], cudaEventDisableTiming);
    cudaEventCreateWithFlags(&eJ, cudaEventDisableTiming);

    pre_all<<<1000, 256, SM_PRE>>>(h0, c0, enc, fld, emb, inp, lW, lb,
                                   Wh, bh, Wf, bf);

    const float* lWh = lW + (size_t)512*2048;
    // finer chunks toward the end to shrink the post-loop tail
    const int chunk_end[6] = {15, 31, 45, 55, 61, 64};
    const int chunk_t0 [6] = {0, 16, 32, 46, 56, 62};
    const int chunk_nt [6] = {16, 16, 14, 10, 6, 3};
    int ci = 0;

    for (int t = 0; t < 65; t++){
        chain_k<<<128, 256, SM_CHAIN>>>(lWh, Ws, bs, Wr, br, Wo, bo, lens, t);
        if (ci < 6 && t == chunk_end[ci]){
            cudaEventRecord(eC[ci], 0);
            cudaStreamWaitEvent(s2, eC[ci], 0);
            logits_chunk<<<250, 256, SM_LOG, s2>>>(oW, ob, lens, out,
                                                   chunk_t0[ci], chunk_nt[ci]);
            ci++;
        }
    }
    cudaEventRecord(eJ, s2);
    cudaStreamWaitEvent(0, eJ, 0);
    fin_k<<<64, 256>>>(out);

    (void)in_sizes; (void)n_in; (void)out_size;
}

// round 17
// speedup vs baseline: 1.0178x; 1.0178x over previous
#include <cuda_runtime.h>
#include <math.h>

#define SOSID 2
#define EPSF  1e-6f

typedef unsigned long long u64;

// ---------------- persistent device state ----------------
__device__ float g_phi_hs[3200*512];
__device__ float g_phi_fds[3200*512];
__device__ float g_zx[2080*2048];
__device__ float g_encT[32*512*104];
__device__ float g_hbuf[2][32*512];
__device__ float g_cbuf[2][32*512];
__device__ float g_ot[32*512];
__device__ float g_gamma[32*512];
__device__ float g_alpha[32*512];
__device__ float g_ctx[32*512];
__device__ float g_att_all[2080*512];  // att for ALL steps
__device__ float g_sch[3200];
__device__ float g_scf[3200];
__device__ float g_zp[8*4*16384];      // LSTM partials: [ks][gate][b*512+h]
__device__ int          g_cnt;
__device__ volatile int g_gen;

// ---------------- helpers ----------------
__device__ __forceinline__ u64 pk2(float lo, float hi){
    u64 r; asm("mov.b64 %0, {%1,%2};" : "=l"(r) : "f"(lo), "f"(hi)); return r;
}
__device__ __forceinline__ void upk2(u64 v, float& lo, float& hi){
    asm("mov.b64 {%0,%1}, %2;" : "=f"(lo), "=f"(hi) : "l"(v));
}
__device__ __forceinline__ u64 ffma2(u64 a, u64 b, u64 c){
    u64 r; asm("fma.rn.f32x2 %0, %1, %2, %3;" : "=l"(r) : "l"(a), "l"(b), "l"(c)); return r;
}
__device__ __forceinline__ u64 fadd2(u64 a, u64 b){
    u64 r; asm("add.rn.f32x2 %0, %1, %2;" : "=l"(r) : "l"(a), "l"(b)); return r;
}
__device__ __forceinline__ float sigf(float x){ return 1.f/(1.f+expf(-x)); }

// global barrier (gridDim.x co-resident blocks)
__device__ __forceinline__ void gsync(){
    __threadfence();
    __syncthreads();
    if (threadIdx.x == 0){
        int g = g_gen;
        if (atomicAdd(&g_cnt, 1) == (int)gridDim.x - 1){
            g_cnt = 0;
            __threadfence();
            g_gen = g + 1;
        } else {
            while (g_gen == g) { __nanosleep(20); }
        }
    }
    __syncthreads();
}

// ---------------- inner-loop building blocks ----------------
__device__ __forceinline__ void load4v(float4 (&w)[4], const float*& wp, int ldw){
    #pragma unroll
    for (int i=0;i<4;i++){ w[i] = *(const float4*)wp; wp += ldw; }
}
__device__ __forceinline__ void comp4v(u64 (&acc)[8][4], const float*& ap, const float4 (&w)[4]){
    #pragma unroll
    for (int i=0;i<4;i++){
        u64 b0=pk2(w[i].x,w[i].x), b1=pk2(w[i].y,w[i].y),
            b2=pk2(w[i].z,w[i].z), b3=pk2(w[i].w,w[i].w);
        u64 aa[8];
        #pragma unroll
        for (int m=0;m<8;m++) aa[m]=((const u64*)ap)[m];
        ap += 36;
        #pragma unroll
        for (int m=0;m<8;m++){
            acc[m][0]=ffma2(aa[m],b0,acc[m][0]);
            acc[m][1]=ffma2(aa[m],b1,acc[m][1]);
            acc[m][2]=ffma2(aa[m],b2,acc[m][2]);
            acc[m][3]=ffma2(aa[m],b3,acc[m][3]);
        }
    }
}
__device__ __forceinline__ void comp4v4(u64 (&acc)[4][4], const float*& ap, const float4 (&w)[4]){
    #pragma unroll
    for (int i=0;i<4;i++){
        u64 b0=pk2(w[i].x,w[i].x), b1=pk2(w[i].y,w[i].y),
            b2=pk2(w[i].z,w[i].z), b3=pk2(w[i].w,w[i].w);
        u64 aa[4];
        #pragma unroll
        for (int m=0;m<4;m++) aa[m]=((const u64*)ap)[m];
        ap += 36;
        #pragma unroll
        for (int m=0;m<4;m++){
            acc[m][0]=ffma2(aa[m],b0,acc[m][0]);
            acc[m][1]=ffma2(aa[m],b1,acc[m][1]);
            acc[m][2]=ffma2(aa[m],b2,acc[m][2]);
            acc[m][3]=ffma2(aa[m],b3,acc[m][3]);
        }
    }
}
__device__ __forceinline__ void load4g(float (&w)[16], const float*& wp){
    #pragma unroll
    for (int i=0;i<4;i++){
        w[i*4+0]=wp[0]; w[i*4+1]=wp[512]; w[i*4+2]=wp[1024]; w[i*4+3]=wp[1536];
        wp += 2048;
    }
}
__device__ __forceinline__ void comp4g2(u64 (&acc)[2][4], const float*& ap, const float (&w)[16]){
    #pragma unroll
    for (int i=0;i<4;i++){
        u64 b0=pk2(w[i*4+0],w[i*4+0]), b1=pk2(w[i*4+1],w[i*4+1]),
            b2=pk2(w[i*4+2],w[i*4+2]), b3=pk2(w[i*4+3],w[i*4+3]);
        u64 a0=((const u64*)ap)[0], a1=((const u64*)ap)[1];
        ap += 36;
        acc[0][0]=ffma2(a0,b0,acc[0][0]); acc[1][0]=ffma2(a1,b0,acc[1][0]);
        acc[0][1]=ffma2(a0,b1,acc[0][1]); acc[1][1]=ffma2(a1,b1,acc[1][1]);
        acc[0][2]=ffma2(a0,b2,acc[0][2]); acc[1][2]=ffma2(a1,b2,acc[1][2]);
        acc[0][3]=ffma2(a0,b3,acc[0][3]); acc[1][3]=ffma2(a1,b3,acc[1][3]);
    }
}

// ================= precompute GEMM (device fn, proven) ====
template<int K, int AMODE, int EPI>
__device__ void dev_g32(float* sm,
    const float* __restrict__ W, const float* __restrict__ Bv,
    const float* __restrict__ A, int lda, int ldw,
    const float* __restrict__ p1, int rowBase, int tt, int colblk)
{
    const int tid = threadIdx.x;
    const int cg  = tid & 63;
    const int rh  = (tid >> 6) & 1;
    const int ks  = tid >> 7;

    for (int idx = tid; idx < 32*K; idx += 256){
        int m = idx / K, k = idx - m*K;
        float v;
        if (AMODE==0) v = A[(size_t)(rowBase+m)*lda + k];
        else          v = (tt==0) ? A[SOSID*512 + k]
                                  : p1[((size_t)m*64 + (tt-1))*512 + k];
        sm[k*36 + m] = v;
    }
    __syncthreads();

    u64 acc[8][4];
    #pragma unroll
    for (int i=0;i<8;i++){ acc[i][0]=0; acc[i][1]=0; acc[i][2]=0; acc[i][3]=0; }

    const float* wp = W + (size_t)(ks*(K/2))*ldw + colblk*256 + cg*4;
    const float* ap = sm + (ks*(K/2))*36 + rh*16;
    const int NT2 = ((K/2)/4)/2;

    float4 wa[4], wb[4];
    load4v(wa, wp, ldw);
    #pragma unroll 1
    for (int j=0;j<NT2-1;j++){
        load4v(wb, wp, ldw);
        comp4v(acc, ap, wa);
        load4v(wa, wp, ldw);
        comp4v(acc, ap, wb);
    }
    load4v(wb, wp, ldw);
    comp4v(acc, ap, wa);
    comp4v(acc, ap, wb);

    __syncthreads();
    u64* red = (u64*)sm;
    u64* mr  = red + (size_t)tid*33;
    #pragma unroll
    for (int m2=0;m2<8;m2++){
        mr[4*m2+0]=acc[m2][0]; mr[4*m2+1]=acc[m2][1];
        mr[4*m2+2]=acc[m2][2]; mr[4*m2+3]=acc[m2][3];
    }
    __syncthreads();
    if (ks == 0){
        const u64* pr = red + (size_t)(tid + 128)*33;
        #pragma unroll
        for (int m2=0;m2<8;m2++){
            acc[m2][0]=fadd2(acc[m2][0],pr[4*m2+0]);
            acc[m2][1]=fadd2(acc[m2][1],pr[4*m2+1]);
            acc[m2][2]=fadd2(acc[m2][2],pr[4*m2+2]);
            acc[m2][3]=fadd2(acc[m2][3],pr[4*m2+3]);
        }
        int c0 = colblk*256 + cg*4;
        #pragma unroll
        for (int m2=0;m2<8;m2++){
            float v0[4], v1[4];
            upk2(acc[m2][0],v0[0],v1[0]); upk2(acc[m2][1],v0[1],v1[1]);
            upk2(acc[m2][2],v0[2],v1[2]); upk2(acc[m2][3],v0[3],v1[3]);
            #pragma unroll
            for (int r=0;r<2;r++){
                int row = rowBase + rh*16 + 2*m2 + r;
                const float* vv = r ? v1 : v0;
                #pragma unroll
                for (int j=0;j<4;j++){
                    int c = c0 + j;
                    float x = vv[j] + Bv[c];
                    if (EPI==0)      g_phi_hs [(size_t)row*512 +c] = tanhf(x);
                    else if (EPI==1) g_phi_fds[(size_t)row*512 +c] = tanhf(x);
                    else             g_zx     [(size_t)row*2048+c] = x;
                }
            }
        }
    }
    __syncthreads();
}

__global__ void __launch_bounds__(256)
pre_all(const float* __restrict__ h0,  const float* __restrict__ c0,
        const float* __restrict__ enc, const float* __restrict__ fld,
        const float* __restrict__ emb, const float* __restrict__ inp,
        const float* __restrict__ lW,  const float* __restrict__ lb,
        const float* __restrict__ Wh,  const float* __restrict__ bh,
        const float* __restrict__ Wf,  const float* __restrict__ bf)
{
    extern __shared__ float sm[];
    const int task = blockIdx.x;
    const int tid  = threadIdx.x;

    if (task < 200){
        dev_g32<512,0,0>(sm, Wh, bh, enc, 512, 512, nullptr, (task>>1)*32, 0, task&1);
    } else if (task < 400){
        int x = task - 200;
        dev_g32<64,0,1>(sm, Wf, bf, fld, 64, 512, nullptr, (x>>1)*32, 0, x&1);
    } else if (task < 920){
        int x = task - 400;
        dev_g32<512,1,2>(sm, lW, lb, emb, 512, 2048, inp, (x>>3)*32, x>>3, x&7);
    } else {
        const int gt = (task-920)*256 + tid, gs = 80*256;
        for (int i=gt; i<16384; i+=gs){ g_hbuf[0][i]=h0[i]; g_cbuf[0][i]=c0[i]; }
        for (int i=gt; i<32*512*104; i+=gs){
            int l=i%104; int hh=(i/104)&511; int b=i/(104*512);
            g_encT[i] = (l<100) ? enc[((size_t)b*100+l)*512+hh] : 0.f;
        }
    }
}

// ================= fused chain kernel (R15-proven phases, batched over steps) ==
__global__ void __launch_bounds__(256, 1)
chain_k(const float* __restrict__ lWh,
        const float* __restrict__ Ws, const float* __restrict__ bs,
        const float* __restrict__ Wr, const float* __restrict__ br,
        const float* __restrict__ Wo, const float* __restrict__ bo,
        const int* __restrict__ lens, int t0, int nt)
{
    extern __shared__ float sm[];
    const int blk = blockIdx.x;
    const int tid = threadIdx.x;
    const int warp = tid >> 5, lane = tid & 31;

    for (int t = t0; t < t0 + nt; t++){
    const int pb = t & 1, cb = pb ^ 1;

    // ---------- P0a: LSTM partials. 128 blocks = 16 h-groups x 8 K-splits ------
    {
        const int hbase = (blk >> 3) * 32;
        const int kq    = blk & 7;
        const int k0    = kq * 64;

        for (int idx = tid; idx < 32*64; idx += 256){
            int m = idx >> 6, k = idx & 63;
            sm[k*36 + m] = g_hbuf[pb][m*512 + k0 + k];
        }
        __syncthreads();

        const int hc = tid & 31;
        const int rg = tid >> 5;

        u64 acc[2][4];
        #pragma unroll
        for (int i=0;i<2;i++){ acc[i][0]=0; acc[i][1]=0; acc[i][2]=0; acc[i][3]=0; }

        const float* wp = lWh + (size_t)k0*2048 + hbase + hc;
        const float* ap = sm + rg*4;

        float wa[16], wb[16];
        load4g(wa, wp);
        #pragma unroll 1
        for (int j=0;j<7;j++){
            load4g(wb, wp);
            comp4g2(acc, ap, wa);
            load4g(wa, wp);
            comp4g2(acc, ap, wb);
        }
        load4g(wb, wp);
        comp4g2(acc, ap, wa);
        comp4g2(acc, ap, wb);

        const int h = hbase + hc;
        #pragma unroll
        for (int p=0;p<2;p++){
            float lo[4], hi[4];
            #pragma unroll
            for (int g=0;g<4;g++) upk2(acc[p][g], lo[g], hi[g]);
            #pragma unroll
            for (int r=0;r<2;r++){
                int b = rg*4 + p*2 + r;
                const float* v = r ? hi : lo;
                #pragma unroll
                for (int g=0;g<4;g++)
                    g_zp[(size_t)(kq*4+g)*16384 + b*512 + h] = v[g];
            }
        }
        __syncthreads();
    }
    gsync();

    // ---------- P0b: gate math + state update ----------------
    if (tid < 128){
        int e = blk*128 + tid;
        int b = e >> 9, h = e & 511;
        float vi=0.f, vj=0.f, vf=0.f, vo=0.f;
        #pragma unroll
        for (int ks2=0; ks2<8; ks2++){
            vi += g_zp[(size_t)(ks2*4+0)*16384 + e];
            vj += g_zp[(size_t)(ks2*4+1)*16384 + e];
            vf += g_zp[(size_t)(ks2*4+2)*16384 + e];
            vo += g_zp[(size_t)(ks2*4+3)*16384 + e];
        }
        const float* zxp = g_zx + ((size_t)(t*32+b))*2048 + h;
        vi += zxp[0]; vj += zxp[512]; vf += zxp[1024]; vo += zxp[1536];
        float cp = g_cbuf[pb][e];
        float hp = g_hbuf[pb][e];
        float cn = sigf(vf+1.f)*cp + sigf(vi)*tanhf(vj);
        float hn = sigf(vo)*tanhf(cn);
        bool fin = (t>0) && (t-1 >= lens[b]);
        g_ot[e]       = fin ? 0.f : hn;
        g_hbuf[cb][e] = fin ? hp  : hn;
        g_cbuf[cb][e] = fin ? cp  : cn;
    }
    gsync();

    // ---------- P1: gamma/alpha. 128 blocks x 8 cols, 32-way K split -----------
    {
        for (int idx = tid; idx < 32*512; idx += 256){
            int m = idx >> 9, k = idx & 511;
            sm[k*36 + m] = g_ot[m*512 + k];
        }
        __syncthreads();

        const int dir = blk >> 6;
        const int colbase = (blk & 63) * 8;
        const float* W  = dir ? Wr : Ws;
        const float* Bv = dir ? br : bs;
        float* dst = dir ? g_alpha : g_gamma;

        const int cq = tid & 1;
        const int rq = (tid >> 1) & 3;
        const int ks = tid >> 3;

        u64 acc[4][4];
        #pragma unroll
        for (int i=0;i<4;i++){ acc[i][0]=0; acc[i][1]=0; acc[i][2]=0; acc[i][3]=0; }

        const float* wp = W + (size_t)(ks*16)*512 + colbase + cq*4;
        const float* ap = sm + (ks*16)*36 + rq*8;

        float4 wa[4], wb[4];
        load4v(wa, wp, 512);
        load4v(wb, wp, 512);
        comp4v4(acc, ap, wa);
        load4v(wa, wp, 512);
        comp4v4(acc, ap, wb);
        load4v(wb, wp, 512);
        comp4v4(acc, ap, wa);
        comp4v4(acc, ap, wb);

        __syncthreads();
        u64* red = (u64*)sm;
        u64* mr  = red + (size_t)tid*17;
        #pragma unroll
        for (int m2=0;m2<4;m2++){
            mr[4*m2+0]=acc[m2][0]; mr[4*m2+1]=acc[m2][1];
            mr[4*m2+2]=acc[m2][2]; mr[4*m2+3]=acc[m2][3];
        }
        __syncthreads();
        for (int s=16; s>=1; s>>=1){
            if (ks < s){
                const u64* pr = red + (size_t)(tid + s*8)*17;
                #pragma unroll
                for (int m2=0;m2<4;m2++){
                    acc[m2][0]=fadd2(acc[m2][0],pr[4*m2+0]);
                    acc[m2][1]=fadd2(acc[m2][1],pr[4*m2+1]);
                    acc[m2][2]=fadd2(acc[m2][2],pr[4*m2+2]);
                    acc[m2][3]=fadd2(acc[m2][3],pr[4*m2+3]);
                }
                if (s>1){
                    #pragma unroll
                    for (int m2=0;m2<4;m2++){
                        mr[4*m2+0]=acc[m2][0]; mr[4*m2+1]=acc[m2][1];
                        mr[4*m2+2]=acc[m2][2]; mr[4*m2+3]=acc[m2][3];
                    }
                }
            }
            __syncthreads();
        }
        if (ks == 0){
            const int c0 = colbase + cq*4;
            #pragma unroll
            for (int m2=0;m2<4;m2++){
                float v0[4], v1[4];
                upk2(acc[m2][0],v0[0],v1[0]); upk2(acc[m2][1],v0[1],v1[1]);
                upk2(acc[m2][2],v0[2],v1[2]); upk2(acc[m2][3],v0[3],v1[3]);
                #pragma unroll
                for (int r=0;r<2;r++){
                    int row = rq*8 + 2*m2 + r;
                    const float* vv = r ? v1 : v0;
                    #pragma unroll
                    for (int j=0;j<4;j++){
                        int c = c0 + j;
                        dst[row*512 + c] = tanhf(vv[j] + Bv[c]);
                    }
                }
            }
        }
        __syncthreads();
    }
    gsync();

    // ---------- P2: attention scores, float4 loads, 128 blocks ----------------
    {
        __shared__ float4 sg4[128], sa4[128];
        const int b  = blk & 31;
        const int lq = blk >> 5;
        if (tid < 128){
            sg4[tid] = ((const float4*)(g_gamma + b*512))[tid];
            sa4[tid] = ((const float4*)(g_alpha + b*512))[tid];
        }
        __syncthreads();
        for (int l0 = warp; l0 < 25; l0 += 8){
            int l = lq*25 + l0;
            const float4* ph = (const float4*)(g_phi_hs  + ((size_t)b*100 + l)*512);
            const float4* pf = (const float4*)(g_phi_fds + ((size_t)b*100 + l)*512);
            float s1=0.f, s2=0.f;
            #pragma unroll
            for (int i=0;i<4;i++){
                float4 a = ph[lane + 32*i];
                float4 g = sg4[lane + 32*i];
                s1 += a.x*g.x + a.y*g.y + a.z*g.z + a.w*g.w;
                float4 c = pf[lane + 32*i];
                float4 d = sa4[lane + 32*i];
                s2 += c.x*d.x + c.y*d.y + c.z*d.z + c.w*d.w;
            }
            #pragma unroll
            for (int o=16;o;o>>=1){ s1 += __shfl_xor_sync(~0u,s1,o); s2 += __shfl_xor_sync(~0u,s2,o); }
            if (lane==0){ g_sch[b*100+l]=s1; g_scf[b*100+l]=s2; }
        }
        __syncthreads();
    }
    gsync();

    // ---------- P3: softmaxes + context (4 h-slices/batch) ----------
    {
        __shared__ float sh2[100], sf2[100], sw2[104], aux2[3];
        const int b  = blk >> 2;
        const int hq = blk & 3;
        for (int i = tid; i < 100; i += 256){
            sh2[i] = g_sch[b*100+i];
            sf2[i] = g_scf[b*100+i];
        }
        __syncthreads();
        if (warp < 2){
            float* s = warp ? sf2 : sh2;
            float mx = -1e30f;
            for (int l=lane;l<100;l+=32) mx = fmaxf(mx, s[l]);
            #pragma unroll
            for (int o=16;o;o>>=1) mx = fmaxf(mx, __shfl_xor_sync(~0u,mx,o));
            float sum = 0.f;
            for (int l=lane;l<100;l+=32){ float e = expf(s[l]-mx); s[l]=e; sum+=e; }
            #pragma unroll
            for (int o=16;o;o>>=1) sum += __shfl_xor_sync(~0u,sum,o);
            if (lane==0) aux2[warp] = EPSF + sum;
        }
        __syncthreads();
        if (warp == 0){
            float d1 = aux2[0], d2 = aux2[1];
            float wsum = 0.f;
            for (int l=lane;l<100;l+=32){ float w = (sh2[l]/d1)*(sf2[l]/d2); sw2[l]=w; wsum += w; }
            #pragma unroll
            for (int o=16;o;o>>=1) wsum += __shfl_xor_sync(~0u,wsum,o);
            if (lane==0) aux2[2] = EPSF + wsum;
        }
        __syncthreads();
        if (warp == 0){
            float d = aux2[2];
            for (int l=lane;l<100;l+=32) sw2[l] = sw2[l]/d;
            if (lane < 4) sw2[100+lane] = 0.f;
        }
        __syncthreads();
        if (tid < 128){
            int h = hq*128 + tid;
            const float4* e = (const float4*)(g_encT + ((size_t)b*512 + h)*104);
            float c2 = 0.f;
            #pragma unroll
            for (int l4=0; l4<26; l4++){
                float4 ev = e[l4];
                int l = l4*4;
                c2 += sw2[l+0]*ev.x + sw2[l+1]*ev.y + sw2[l+2]*ev.z + sw2[l+3]*ev.w;
            }
            g_ctx[b*512+h] = c2;
        }
        __syncthreads();
    }
    gsync();

    // ---------- P4: att(t). 128 blocks x 4 cols, K=1024, 64-way K split --------
    {
        for (int idx = tid; idx < 32*1024; idx += 256){
            int m = idx >> 10, k = idx & 1023;
            float v = (k < 512) ? g_ctx[m*512+k] : g_ot[m*512+k-512];
            sm[k*36 + m] = v;
        }
        __syncthreads();

        const int colbase = blk * 4;
        const int rq = tid & 3;
        const int ks = tid >> 2;

        u64 acc[4][4];
        #pragma unroll
        for (int i=0;i<4;i++){ acc[i][0]=0; acc[i][1]=0; acc[i][2]=0; acc[i][3]=0; }

        const float* wp = Wo + (size_t)(ks*16)*512 + colbase;
        const float* ap = sm + (ks*16)*36 + rq*8;

        float4 wa[4], wb[4];
        load4v(wa, wp, 512);
        load4v(wb, wp, 512);
        comp4v4(acc, ap, wa);
        load4v(wa, wp, 512);
        comp4v4(acc, ap, wb);
        load4v(wb, wp, 512);
        comp4v4(acc, ap, wa);
        comp4v4(acc, ap, wb);

        __syncthreads();
        u64* red = (u64*)sm;
        u64* mr  = red + (size_t)tid*17;
        #pragma unroll
        for (int m2=0;m2<4;m2++){
            mr[4*m2+0]=acc[m2][0]; mr[4*m2+1]=acc[m2][1];
            mr[4*m2+2]=acc[m2][2]; mr[4*m2+3]=acc[m2][3];
        }
        __syncthreads();
        for (int s=32; s>=1; s>>=1){
            if (ks < s){
                const u64* pr = red + (size_t)(tid + s*4)*17;
                #pragma unroll
                for (int m2=0;m2<4;m2++){
                    acc[m2][0]=fadd2(acc[m2][0],pr[4*m2+0]);
                    acc[m2][1]=fadd2(acc[m2][1],pr[4*m2+1]);
                    acc[m2][2]=fadd2(acc[m2][2],pr[4*m2+2]);
                    acc[m2][3]=fadd2(acc[m2][3],pr[4*m2+3]);
                }
                if (s>1){
                    #pragma unroll
                    for (int m2=0;m2<4;m2++){
                        mr[4*m2+0]=acc[m2][0]; mr[4*m2+1]=acc[m2][1];
                        mr[4*m2+2]=acc[m2][2]; mr[4*m2+3]=acc[m2][3];
                    }
                }
            }
            __syncthreads();
        }
        if (ks == 0){
            float* dst = g_att_all + (size_t)t*16384;
            #pragma unroll
            for (int m2=0;m2<4;m2++){
                float v0[4], v1[4];
                upk2(acc[m2][0],v0[0],v1[0]); upk2(acc[m2][1],v0[1],v1[1]);
                upk2(acc[m2][2],v0[2],v1[2]); upk2(acc[m2][3],v0[3],v1[3]);
                #pragma unroll
                for (int r=0;r<2;r++){
                    int row = rq*8 + 2*m2 + r;
                    bool fin = (t>0) && (t-1 >= lens[row]);
                    const float* vv = r ? v1 : v0;
                    #pragma unroll
                    for (int j=0;j<4;j++){
                        int c = colbase + j;
                        float v = tanhf(vv[j] + bo[c]);
                        dst[row*512 + c] = fin ? 0.f : v;
                    }
                }
            }
        }
        __syncthreads();
    }
    gsync();
    }   // step loop
}

// ---- logits chunk: grid 250 x 256; 128 cols/block for nt steps ----
__global__ void __launch_bounds__(256)
logits_chunk(const float* __restrict__ oW, const float* __restrict__ ob,
             const int* __restrict__ lens, float* __restrict__ out, int t0, int nt)
{
    extern __shared__ float sm[];
    const int tid = threadIdx.x, blk = blockIdx.x;
    const int cg = tid & 31;
    const int rh = (tid >> 5) & 1;
    const int ks = tid >> 6;

    for (int tt = t0; tt < t0 + nt; tt++){
        const float* attb = g_att_all + (size_t)tt*16384;
        __syncthreads();
        for (int idx = tid; idx < 32*512; idx += 256){
            int m = idx >> 9, k = idx & 511;
            sm[k*36 + m] = attb[m*512 + k];
        }
        __syncthreads();

        u64 acc[8][4];
        #pragma unroll
        for (int i=0;i<8;i++){ acc[i][0]=0; acc[i][1]=0; acc[i][2]=0; acc[i][3]=0; }

        const float* wp = oW + (size_t)(ks*128)*32000 + blk*128 + cg*4;
        const float* ap = sm + (ks*128)*36 + rh*16;

        float4 wa[4], wb[4];
        load4v(wa, wp, 32000);
        #pragma unroll 1
        for (int j=0;j<15;j++){
            load4v(wb, wp, 32000);
            comp4v(acc, ap, wa);
            load4v(wa, wp, 32000);
            comp4v(acc, ap, wb);
        }
        load4v(wb, wp, 32000);
        comp4v(acc, ap, wa);
        comp4v(acc, ap, wb);

        __syncthreads();
        u64* red = (u64*)sm;
        u64* mr  = red + (size_t)tid*33;
        #pragma unroll
        for (int m2=0;m2<8;m2++){
            mr[4*m2+0]=acc[m2][0]; mr[4*m2+1]=acc[m2][1];
            mr[4*m2+2]=acc[m2][2]; mr[4*m2+3]=acc[m2][3];
        }
        __syncthreads();
        for (int s=2; s>=1; s>>=1){
            if (ks < s){
                const u64* pr = red + (size_t)(tid + s*64)*33;
                #pragma unroll
                for (int m2=0;m2<8;m2++){
                    acc[m2][0]=fadd2(acc[m2][0],pr[4*m2+0]);
                    acc[m2][1]=fadd2(acc[m2][1],pr[4*m2+1]);
                    acc[m2][2]=fadd2(acc[m2][2],pr[4*m2+2]);
                    acc[m2][3]=fadd2(acc[m2][3],pr[4*m2+3]);
                }
                if (s>1){
                    #pragma unroll
                    for (int m2=0;m2<8;m2++){
                        mr[4*m2+0]=acc[m2][0]; mr[4*m2+1]=acc[m2][1];
                        mr[4*m2+2]=acc[m2][2]; mr[4*m2+3]=acc[m2][3];
                    }
                }
            }
            __syncthreads();
        }
        if (ks == 0){
            const int c0 = blk*128 + cg*4;
            #pragma unroll
            for (int m2=0;m2<8;m2++){
                float v0[4], v1[4];
                upk2(acc[m2][0],v0[0],v1[0]); upk2(acc[m2][1],v0[1],v1[1]);
                upk2(acc[m2][2],v0[2],v1[2]); upk2(acc[m2][3],v0[3],v1[3]);
                #pragma unroll
                for (int r=0;r<2;r++){
                    int row = rh*16 + 2*m2 + r;
                    bool fin = (tt>0) && (tt-1 >= lens[row]);
                    const float* vv = r ? v1 : v0;
                    float* op = out + (size_t)row*2080000 + (size_t)tt*32000 + c0;
                    #pragma unroll
                    for (int j=0;j<4;j++)
                        op[j] = fin ? 0.f : (vv[j] + ob[c0+j]);
                }
            }
        }
    }
}

// ---- final h/c ----
__global__ void fin_k(float* __restrict__ out)
{
    int i = blockIdx.x*256 + threadIdx.x;
    if (i < 16384){
        out[66560000 + i]         = g_hbuf[1][i];
        out[66560000 + 16384 + i] = g_cbuf[1][i];
    }
}

// ---------------- host ----------------
extern "C" void kernel_launch(void* const* d_in, const int* in_sizes, int n_in,
                              void* d_out, int out_size)
{
    const float* h0   = (const float*)d_in[0];
    const float* c0   = (const float*)d_in[1];
    const float* inp  = (const float*)d_in[2];
    const float* enc  = (const float*)d_in[3];
    const float* fld  = (const float*)d_in[4];
    const float* emb  = (const float*)d_in[5];
    const float* lW   = (const float*)d_in[6];
    const float* lb   = (const float*)d_in[7];
    const float* Wh   = (const float*)d_in[8];
    const float* bh   = (const float*)d_in[9];
    const float* Ws   = (const float*)d_in[10];
    const float* bs   = (const float*)d_in[11];
    const float* Wr   = (const float*)d_in[12];
    const float* br   = (const float*)d_in[13];
    const float* Wf   = (const float*)d_in[14];
    const float* bf   = (const float*)d_in[15];
    const float* Wo   = (const float*)d_in[16];
    const float* bo   = (const float*)d_in[17];
    const float* oW   = (const float*)d_in[18];
    const float* ob   = (const float*)d_in[19];
    const int*   lens = (const int*)  d_in[20];
    float* out = (float*)d_out;

    const int SM_PRE   = 512*36*4;      // 73728
    const int SM_CHAIN = 1024*36*4;     // 147456
    const int SM_LOG   = 512*36*4;      // 73728

    cudaFuncSetAttribute((const void*)pre_all,      cudaFuncAttributeMaxDynamicSharedMemorySize, SM_PRE);
    cudaFuncSetAttribute((const void*)chain_k,      cudaFuncAttributeMaxDynamicSharedMemorySize, SM_CHAIN);
    cudaFuncSetAttribute((const void*)logits_chunk, cudaFuncAttributeMaxDynamicSharedMemorySize, SM_LOG);

    cudaStream_t s2;
    cudaStreamCreateWithFlags(&s2, cudaStreamNonBlocking);
    cudaEvent_t eC[5], eJ;
    for (int i=0;i<5;i++) cudaEventCreateWithFlags(&eC[i], cudaEventDisableTiming);
    cudaEventCreateWithFlags(&eJ, cudaEventDisableTiming);

    pre_all<<<1000, 256, SM_PRE>>>(h0, c0, enc, fld, emb, inp, lW, lb,
                                   Wh, bh, Wf, bf);

    const float* lWh = lW + (size_t)512*2048;
    // 5 batched chain launches; logits chunk after each batch on side stream
    const int bt0[5] = {0, 16, 32, 48, 64};
    const int bnt[5] = {16, 16, 16, 16, 1};

    for (int i = 0; i < 5; i++){
        chain_k<<<128, 256, SM_CHAIN>>>(lWh, Ws, bs, Wr, br, Wo, bo, lens,
                                        bt0[i], bnt[i]);
        cudaEventRecord(eC[i], 0);
        cudaStreamWaitEvent(s2, eC[i], 0);
        logits_chunk<<<250, 256, SM_LOG, s2>>>(oW, ob, lens, out, bt0[i], bnt[i]);
    }
    cudaEventRecord(eJ, s2);
    cudaStreamWaitEvent(0, eJ, 0);
    fin_k<<<64, 256>>>(out);

    (void)in_sizes; (void)n_in; (void)out_size;
}